// round 6
// baseline (speedup 1.0000x reference)
#include <cuda_runtime.h>
#include <cuda_bf16.h>
#include <math.h>
#include <stdint.h>

#define EPS 1e-8f

#define C_CLUST 1024
#define S_SAMP  16
#define D_DIM   512
#define NROWS   (C_CLUST * S_SAMP)   // 16384

// ---- k2 tiling ----
#define BM 128                  // rows per CTA
#define NT 128                  // N-tile (centroids per tile) -> 8 tiles
#define KC 64                   // K-chunk (bf16, 128B rows)
#define NTILES 8
#define NC 64                   // total chunks = 8 tiles * 8 k-chunks
#define NTHREADS 512
#define A_BYTES   (BM * D_DIM * 2)        // 128 KB
#define B_CHUNK_B (NT * KC * 2)           // 16 KB
#define NBUF 4                            // B ring depth
#define DYN_SMEM  (A_BYTES + NBUF * B_CHUNK_B + 1024)

// ---------------------------------------------------------------------------
// Scratch (static device globals)
// ---------------------------------------------------------------------------
__device__ __nv_bfloat16 g_Abf[NROWS * D_DIM];    // 16 MB
__device__ __nv_bfloat16 g_Bbf[C_CLUST * D_DIM];  // 1 MB (mean centroids [k][d])
__device__ float g_invnm[C_CLUST];
__device__ float g_invnx[NROWS];
__device__ float g_sp[NROWS];                     // sim_pos (exact fp32)

// ---------------------------------------------------------------------------
// helpers
// ---------------------------------------------------------------------------
__device__ __forceinline__ uint32_t smem_u32(const void* p) {
    uint32_t a;
    asm("{ .reg .u64 t; cvta.to.shared.u64 t, %1; cvt.u32.u64 %0, t; }" : "=r"(a) : "l"(p));
    return a;
}
__device__ __forceinline__ void cp_async16(uint32_t dst, const void* src) {
    asm volatile("cp.async.cg.shared.global [%0], [%1], 16;\n" :: "r"(dst), "l"(src) : "memory");
}
__device__ __forceinline__ void cp_commit() {
    asm volatile("cp.async.commit_group;\n" ::: "memory");
}
template <int N> __device__ __forceinline__ void cp_wait() {
    asm volatile("cp.async.wait_group %0;\n" :: "n"(N) : "memory");
}
__device__ __forceinline__ void ldsm4(uint32_t* r, uint32_t addr) {
    asm volatile("ldmatrix.sync.aligned.m8n8.x4.shared.b16 {%0,%1,%2,%3}, [%4];"
                 : "=r"(r[0]), "=r"(r[1]), "=r"(r[2]), "=r"(r[3]) : "r"(addr));
}
__device__ __forceinline__ void mma16816(float* c, const uint32_t* a, uint32_t b0, uint32_t b1) {
    asm volatile("mma.sync.aligned.m16n8k16.row.col.f32.bf16.bf16.f32 "
                 "{%0,%1,%2,%3}, {%4,%5,%6,%7}, {%8,%9}, {%0,%1,%2,%3};"
                 : "+f"(c[0]), "+f"(c[1]), "+f"(c[2]), "+f"(c[3])
                 : "r"(a[0]), "r"(a[1]), "r"(a[2]), "r"(a[3]), "r"(b0), "r"(b1));
}
// swizzled address inside a [rows][64 bf16] tile (128B rows)
__device__ __forceinline__ uint32_t sw_addr(uint32_t base, int row, int kseg) {
    return base + (uint32_t)(row << 7) + (uint32_t)(((kseg ^ (row & 7)) & 7) << 4);
}

// ---------------------------------------------------------------------------
// Kernel 1: per-cluster stats + bf16 conversion (A rows, B centroids).
// ---------------------------------------------------------------------------
__global__ void __launch_bounds__(256) k1_stats(const float* __restrict__ x,
                                                float* __restrict__ out)
{
    __shared__ float xs[S_SAMP * D_DIM];   // 32 KB
    __shared__ float ssum[D_DIM];
    __shared__ float sred[8];
    __shared__ float s_sumsq;

    const int j   = blockIdx.x;
    const int tid = threadIdx.x;

    if (j == 0 && tid == 0) out[0] = 0.f;   // k2 accumulates into out

    // Load + convert in one pass
    const float4* gx = (const float4*)(x + (size_t)j * S_SAMP * D_DIM);
    float4* xs4 = (float4*)xs;
    #pragma unroll
    for (int it = 0; it < 8; it++) {
        const int i4 = tid + it * 256;
        const float4 v = gx[i4];
        xs4[i4] = v;
        unsigned short h0 = __bfloat16_as_ushort(__float2bfloat16(v.x));
        unsigned short h1 = __bfloat16_as_ushort(__float2bfloat16(v.y));
        unsigned short h2 = __bfloat16_as_ushort(__float2bfloat16(v.z));
        unsigned short h3 = __bfloat16_as_ushort(__float2bfloat16(v.w));
        ((uint2*)g_Abf)[(size_t)j * 2048 + i4] =
            make_uint2(((uint32_t)h1 << 16) | h0, ((uint32_t)h3 << 16) | h2);
    }
    __syncthreads();

    // column sums over S
    const int d0 = tid, d1 = tid + 256;
    float s0 = 0.f, s1 = 0.f;
    #pragma unroll
    for (int i = 0; i < S_SAMP; i++) {
        s0 += xs[i * D_DIM + d0];
        s1 += xs[i * D_DIM + d1];
    }
    ssum[d0] = s0;
    ssum[d1] = s1;
    g_Bbf[(size_t)j * D_DIM + d0] = __float2bfloat16(s0 * (1.f / 16.f));
    g_Bbf[(size_t)j * D_DIM + d1] = __float2bfloat16(s1 * (1.f / 16.f));

    float p = s0 * s0 + s1 * s1;
    #pragma unroll
    for (int off = 16; off; off >>= 1) p += __shfl_down_sync(0xffffffffu, p, off);
    if ((tid & 31) == 0) sred[tid >> 5] = p;
    __syncthreads();
    if (tid == 0) {
        float t = 0.f;
        #pragma unroll
        for (int wi = 0; wi < 8; wi++) t += sred[wi];
        s_sumsq = t;
        g_invnm[j] = 16.f / sqrtf(t);
    }
    __syncthreads();
    const float sumsq = s_sumsq;

    const int w = tid >> 5, l = tid & 31;
    #pragma unroll
    for (int rr = 0; rr < 2; rr++) {
        const int i = w + rr * 8;
        float nx2 = 0.f, dt = 0.f;
        #pragma unroll
        for (int c = 0; c < 16; c++) {
            const int d = l + c * 32;
            const float a = xs[i * D_DIM + d];
            nx2 += a * a;
            dt  += a * ssum[d];
        }
        #pragma unroll
        for (int off = 16; off; off >>= 1) {
            nx2 += __shfl_down_sync(0xffffffffu, nx2, off);
            dt  += __shfl_down_sync(0xffffffffu, dt,  off);
        }
        if (l == 0) {
            const float loo_dot = (dt - nx2) * (1.f / 15.f);
            const float nloo2   = fmaxf((sumsq - 2.f * dt + nx2) * (1.f / 225.f), 0.f);
            const float nx      = sqrtf(nx2);
            g_invnx[j * S_SAMP + i] = 1.f / nx;
            g_sp[j * S_SAMP + i]    = loo_dot / fmaxf(nx * sqrtf(nloo2), EPS);
        }
    }
}

// ---------------------------------------------------------------------------
// Kernel 2: bf16 mma.sync GEMM + fused logsumexp.
// 128 CTAs x 512 threads (16 warps: wm=warp&3 -> 32 rows, wn=warp>>2 -> 32 cols).
// Single acc buffer (32 regs) -> <=128 regs/thread -> 4 warps/SMSP.
// ---------------------------------------------------------------------------
__global__ void __launch_bounds__(NTHREADS, 1) k2_gemm_lse(const float* __restrict__ wptr,
                                                           float* __restrict__ out)
{
    extern __shared__ char rawsm[];
    const uint32_t smA = (smem_u32(rawsm) + 1023u) & ~1023u;  // 128 KB (8 chunks x 16KB)
    const uint32_t smB = smA + A_BYTES;                        // 4 x 16 KB ring

    __shared__ float s_invnx[BM], s_sp[BM];
    __shared__ float s_invnm[NT];
    __shared__ float s_red[4][BM], s_rowloss[BM], s_part[8];

    const int tid  = threadIdx.x;
    const int blk  = blockIdx.x;
    const int w5   = tid >> 5, lane = tid & 31;
    const int wm   = w5 & 3;        // rows wm*32..wm*32+31
    const int wn   = w5 >> 2;       // cols wn*32 within NT
    const int lq   = lane >> 3, l7 = lane & 7;

    if (tid < BM) {
        s_invnx[tid] = g_invnx[blk * BM + tid];
        s_sp[tid]    = g_sp[blk * BM + tid];
    }

    // ---- chunk loader: B chunk gg; for gg<8 also A chunk gg (same group) ----
    const __nv_bfloat16* Asrc = g_Abf + (size_t)blk * BM * D_DIM;
    auto load_AB = [&](int gg) {
        const uint32_t slot = smB + (uint32_t)(gg & 3) * B_CHUNK_B;
        const __nv_bfloat16* bsrc =
            g_Bbf + (size_t)((gg >> 3) * NT) * D_DIM + (gg & 7) * KC;
        #pragma unroll
        for (int it = 0; it < 2; it++) {
            const int i = tid + it * NTHREADS;     // 0..1023
            const int r = i >> 3, s = i & 7;
            cp_async16(slot + (uint32_t)(r << 7) + (uint32_t)(((s ^ (r & 7)) & 7) << 4),
                       bsrc + (size_t)r * D_DIM + s * 8);
        }
        if (gg < 8) {
            #pragma unroll
            for (int it = 0; it < 2; it++) {
                const int i = tid + it * NTHREADS;
                const int r = i >> 3, s = i & 7;
                cp_async16(smA + (uint32_t)gg * 16384u + (uint32_t)(r << 7) +
                               (uint32_t)(((s ^ (r & 7)) & 7) << 4),
                           Asrc + (size_t)r * D_DIM + gg * KC + s * 8);
            }
        }
        cp_commit();
    };

    load_AB(0); load_AB(1); load_AB(2);

    const float wp = log1pf(expf(wptr[0]));
    __syncthreads();   // s_invnx/s_sp visible

    // per-thread row constants
    float inxr[2][2], spr[2][2];
    int   jrr[2][2];
    #pragma unroll
    for (int mt = 0; mt < 2; mt++)
        #pragma unroll
        for (int h = 0; h < 2; h++) {
            const int rl = wm * 32 + mt * 16 + h * 8 + (lane >> 2);
            inxr[mt][h] = s_invnx[rl];
            spr[mt][h]  = s_sp[rl];
            jrr[mt][h]  = blk * 8 + (rl >> 4);
        }

    float acc[2][4][4];
    #pragma unroll
    for (int mt = 0; mt < 2; mt++)
        #pragma unroll
        for (int p = 0; p < 4; p++)
            #pragma unroll
            for (int e = 0; e < 4; e++) acc[mt][p][e] = 0.f;

    float es[2][2] = {{0.f, 0.f}, {0.f, 0.f}};

    // ---- MMA over one resident chunk (warp tile 32 rows x 32 cols) ----
    auto mma_chunk = [&](int kcA, int slot) {
        const uint32_t Ac = smA + (uint32_t)kcA * 16384u;
        const uint32_t Bs = smB + (uint32_t)slot * B_CHUNK_B;
        #pragma unroll
        for (int k16 = 0; k16 < 4; k16++) {
            uint32_t a[2][4];
            #pragma unroll
            for (int mt = 0; mt < 2; mt++)
                ldsm4(a[mt], sw_addr(Ac, wm * 32 + mt * 16 + (lq & 1) * 8 + l7,
                                     k16 * 2 + (lq >> 1)));
            uint32_t b[2][4];
            #pragma unroll
            for (int p2 = 0; p2 < 2; p2++)
                ldsm4(b[p2], sw_addr(Bs, wn * 32 + p2 * 16 + (lq >> 1) * 8 + l7,
                                     k16 * 2 + (lq & 1)));
            #pragma unroll
            for (int p2 = 0; p2 < 2; p2++)
                #pragma unroll
                for (int mt = 0; mt < 2; mt++) {
                    mma16816(acc[mt][p2 * 2],     a[mt], b[p2][0], b[p2][1]);
                    mma16816(acc[mt][p2 * 2 + 1], a[mt], b[p2][2], b[p2][3]);
                }
        }
    };

    // ---- epilogue of tile t: normalize, diagonal swap, exp-accumulate ----
    auto epi_tile = [&](int t) {
        #pragma unroll
        for (int p = 0; p < 4; p++) {
            const int c0  = wn * 32 + p * 8 + (lane & 3) * 2;
            const float nm0 = s_invnm[c0];
            const float nm1 = s_invnm[c0 + 1];
            const int gc0 = t * NT + c0;
            #pragma unroll
            for (int mt = 0; mt < 2; mt++)
                #pragma unroll
                for (int h = 0; h < 2; h++) {
                    float s0 = acc[mt][p][h * 2 + 0] * inxr[mt][h] * nm0;
                    float s1 = acc[mt][p][h * 2 + 1] * inxr[mt][h] * nm1;
                    if (gc0     == jrr[mt][h]) s0 = spr[mt][h];
                    if (gc0 + 1 == jrr[mt][h]) s1 = spr[mt][h];
                    es[mt][h] += __expf(wp * s0) + __expf(wp * s1);
                    acc[mt][p][h * 2 + 0] = 0.f;
                    acc[mt][p][h * 2 + 1] = 0.f;
                }
        }
    };

    // ---- pipeline head: wait for chunk g, barrier, prefetch chunk g+3 ----
    auto pipe_head = [&](int g) {
        if (g < NC - 2) cp_wait<2>();
        else if (g == NC - 2) cp_wait<1>();
        else cp_wait<0>();
        __syncthreads();           // chunk g visible; all warps done with chunk g-1
        if (g + 3 < NC) load_AB(g + 3);
    };

    #pragma unroll 1
    for (int t = 0; t < NTILES; t++) {
        #pragma unroll
        for (int kc = 0; kc < 8; kc++) {
            const int g = t * 8 + kc;
            pipe_head(g);
            if (kc == 0 && tid < NT) s_invnm[tid] = g_invnm[t * NT + tid];
            mma_chunk(kc, g & 3);
        }
        epi_tile(t);   // safe: next tile's s_invnm store is behind a barrier
    }

    // ---- reduce exp-sums: 4 lanes per row, then the four wn quarters ----
    #pragma unroll
    for (int mt = 0; mt < 2; mt++)
        #pragma unroll
        for (int h = 0; h < 2; h++) {
            float v = es[mt][h];
            v += __shfl_xor_sync(0xffffffffu, v, 1);
            v += __shfl_xor_sync(0xffffffffu, v, 2);
            if ((lane & 3) == 0)
                s_red[wn][wm * 32 + mt * 16 + h * 8 + (lane >> 2)] = v;
        }
    __syncthreads();
    if (tid < BM) {
        const float tot = s_red[0][tid] + s_red[1][tid] + s_red[2][tid] + s_red[3][tid];
        s_rowloss[tid] = logf(tot) - wp * s_sp[tid];
    }
    __syncthreads();
    if (tid < 8) {
        float t = 0.f;
        #pragma unroll
        for (int r = 0; r < 16; r++) t += s_rowloss[tid * 16 + r];
        s_part[tid] = t;
    }
    __syncthreads();
    if (tid == 0) {
        float t = 0.f;
        #pragma unroll
        for (int i = 0; i < 8; i++) t += s_part[i];
        atomicAdd(out, t * (1.f / (float)NROWS));
    }
}

extern "C" void kernel_launch(void* const* d_in, const int* in_sizes, int n_in,
                              void* d_out, int out_size)
{
    const float* x = (const float*)d_in[0];
    const float* w = (const float*)d_in[1];
    // b cancels: lse(wp*sim + b) - (wp*sim_pos + b) is b-independent.
    float* out = (float*)d_out;

    cudaFuncSetAttribute(k2_gemm_lse, cudaFuncAttributeMaxDynamicSharedMemorySize, DYN_SMEM);

    k1_stats<<<C_CLUST, 256>>>(x, out);
    k2_gemm_lse<<<NROWS / BM, NTHREADS, DYN_SMEM>>>(w, out);
}

// round 8
// speedup vs baseline: 1.1175x; 1.1175x over previous
#include <cuda_runtime.h>
#include <cuda_bf16.h>
#include <math.h>
#include <stdint.h>

#define EPS 1e-8f

#define C_CLUST 1024
#define S_SAMP  16
#define D_DIM   512
#define NROWS   (C_CLUST * S_SAMP)   // 16384

// ---- k2 tiling ----
#define BM 128                  // rows per CTA
#define NT 256                  // N-tile (centroids per tile) -> 4 tiles
#define KC 64                   // K-chunk (bf16, 128B rows)
#define NTILES 4
#define NC 32                   // total chunks = 4 tiles * 8 k-chunks
#define NTHREADS 256
#define A_BYTES   (BM * D_DIM * 2)        // 131072 (8 chunks x 16KB)
#define B_CHUNK_B (NT * KC * 2)           // 32768
#define NBUF 3                            // B ring depth
#define SMALL_B   2048                    // s_invnx/s_sp/s_invnm region
// 2048 + 131072 + 98304 + 128 slack = 231552 <= 232448 opt-in max, 0 static smem
#define DYN_SMEM  (SMALL_B + A_BYTES + NBUF * B_CHUNK_B + 128)

// ---------------------------------------------------------------------------
// Scratch (static device globals)
// ---------------------------------------------------------------------------
__device__ __nv_bfloat16 g_Abf[NROWS * D_DIM];    // 16 MB
__device__ __nv_bfloat16 g_Bbf[C_CLUST * D_DIM];  // 1 MB (mean centroids [k][d])
__device__ float g_invnm[C_CLUST];
__device__ float g_invnx[NROWS];
__device__ float g_sp[NROWS];                     // sim_pos (exact fp32)

// ---------------------------------------------------------------------------
// helpers
// ---------------------------------------------------------------------------
__device__ __forceinline__ uint32_t smem_u32(const void* p) {
    uint32_t a;
    asm("{ .reg .u64 t; cvta.to.shared.u64 t, %1; cvt.u32.u64 %0, t; }" : "=r"(a) : "l"(p));
    return a;
}
__device__ __forceinline__ void cp_async16(uint32_t dst, const void* src) {
    asm volatile("cp.async.cg.shared.global [%0], [%1], 16;\n" :: "r"(dst), "l"(src) : "memory");
}
__device__ __forceinline__ void cp_commit() {
    asm volatile("cp.async.commit_group;\n" ::: "memory");
}
template <int N> __device__ __forceinline__ void cp_wait() {
    asm volatile("cp.async.wait_group %0;\n" :: "n"(N) : "memory");
}
__device__ __forceinline__ void ldsm4(uint32_t* r, uint32_t addr) {
    asm volatile("ldmatrix.sync.aligned.m8n8.x4.shared.b16 {%0,%1,%2,%3}, [%4];"
                 : "=r"(r[0]), "=r"(r[1]), "=r"(r[2]), "=r"(r[3]) : "r"(addr));
}
__device__ __forceinline__ void mma16816(float* c, const uint32_t* a, uint32_t b0, uint32_t b1) {
    asm volatile("mma.sync.aligned.m16n8k16.row.col.f32.bf16.bf16.f32 "
                 "{%0,%1,%2,%3}, {%4,%5,%6,%7}, {%8,%9}, {%0,%1,%2,%3};"
                 : "+f"(c[0]), "+f"(c[1]), "+f"(c[2]), "+f"(c[3])
                 : "r"(a[0]), "r"(a[1]), "r"(a[2]), "r"(a[3]), "r"(b0), "r"(b1));
}
// swizzled address inside a [rows][64 bf16] tile (128B rows)
__device__ __forceinline__ uint32_t sw_addr(uint32_t base, int row, int kseg) {
    return base + (uint32_t)(row << 7) + (uint32_t)(((kseg ^ (row & 7)) & 7) << 4);
}

// ---------------------------------------------------------------------------
// Kernel 1: per-cluster stats + bf16 conversion (A rows, B centroids).
// ---------------------------------------------------------------------------
__global__ void __launch_bounds__(256) k1_stats(const float* __restrict__ x,
                                                float* __restrict__ out)
{
    __shared__ float xs[S_SAMP * D_DIM];   // 32 KB
    __shared__ float ssum[D_DIM];
    __shared__ float sred[8];
    __shared__ float s_sumsq;

    const int j   = blockIdx.x;
    const int tid = threadIdx.x;

    if (j == 0 && tid == 0) out[0] = 0.f;   // k2 accumulates into out

    // Load + convert in one pass
    const float4* gx = (const float4*)(x + (size_t)j * S_SAMP * D_DIM);
    float4* xs4 = (float4*)xs;
    #pragma unroll
    for (int it = 0; it < 8; it++) {
        const int i4 = tid + it * 256;
        const float4 v = gx[i4];
        xs4[i4] = v;
        unsigned short h0 = __bfloat16_as_ushort(__float2bfloat16(v.x));
        unsigned short h1 = __bfloat16_as_ushort(__float2bfloat16(v.y));
        unsigned short h2 = __bfloat16_as_ushort(__float2bfloat16(v.z));
        unsigned short h3 = __bfloat16_as_ushort(__float2bfloat16(v.w));
        ((uint2*)g_Abf)[(size_t)j * 2048 + i4] =
            make_uint2(((uint32_t)h1 << 16) | h0, ((uint32_t)h3 << 16) | h2);
    }
    __syncthreads();

    // column sums over S
    const int d0 = tid, d1 = tid + 256;
    float s0 = 0.f, s1 = 0.f;
    #pragma unroll
    for (int i = 0; i < S_SAMP; i++) {
        s0 += xs[i * D_DIM + d0];
        s1 += xs[i * D_DIM + d1];
    }
    ssum[d0] = s0;
    ssum[d1] = s1;
    g_Bbf[(size_t)j * D_DIM + d0] = __float2bfloat16(s0 * (1.f / 16.f));
    g_Bbf[(size_t)j * D_DIM + d1] = __float2bfloat16(s1 * (1.f / 16.f));

    float p = s0 * s0 + s1 * s1;
    #pragma unroll
    for (int off = 16; off; off >>= 1) p += __shfl_down_sync(0xffffffffu, p, off);
    if ((tid & 31) == 0) sred[tid >> 5] = p;
    __syncthreads();
    if (tid == 0) {
        float t = 0.f;
        #pragma unroll
        for (int wi = 0; wi < 8; wi++) t += sred[wi];
        s_sumsq = t;
        g_invnm[j] = 16.f / sqrtf(t);
    }
    __syncthreads();
    const float sumsq = s_sumsq;

    const int w = tid >> 5, l = tid & 31;
    #pragma unroll
    for (int rr = 0; rr < 2; rr++) {
        const int i = w + rr * 8;
        float nx2 = 0.f, dt = 0.f;
        #pragma unroll
        for (int c = 0; c < 16; c++) {
            const int d = l + c * 32;
            const float a = xs[i * D_DIM + d];
            nx2 += a * a;
            dt  += a * ssum[d];
        }
        #pragma unroll
        for (int off = 16; off; off >>= 1) {
            nx2 += __shfl_down_sync(0xffffffffu, nx2, off);
            dt  += __shfl_down_sync(0xffffffffu, dt,  off);
        }
        if (l == 0) {
            const float loo_dot = (dt - nx2) * (1.f / 15.f);
            const float nloo2   = fmaxf((sumsq - 2.f * dt + nx2) * (1.f / 225.f), 0.f);
            const float nx      = sqrtf(nx2);
            g_invnx[j * S_SAMP + i] = 1.f / nx;
            g_sp[j * S_SAMP + i]    = loo_dot / fmaxf(nx * sqrtf(nloo2), EPS);
        }
    }
}

// ---------------------------------------------------------------------------
// Kernel 2: bf16 mma.sync GEMM + fused logsumexp.
// 128 CTAs x 256 threads. 8 warps, warp tile 64x64:
//   wm = warp&1  -> rows wm*64 .. +63
//   wn = warp>>1 -> cols wn*64 .. +63 (within the 256-wide N-tile)
// 32 ldsm : 128 HMMA per chunk per warp; one __syncthreads per chunk.
// ALL shared storage is dynamic (0 static) to fit the 227KB opt-in limit.
// ---------------------------------------------------------------------------
__global__ void __launch_bounds__(NTHREADS, 1) k2_gemm_lse(const float* __restrict__ wptr,
                                                           float* __restrict__ out)
{
    extern __shared__ char rawsm[];
    char* smbase = (char*)(((uintptr_t)rawsm + 127u) & ~(uintptr_t)127u);

    // layout: [0,2048) small consts | [2048, +128K) A | then 3x32K B ring
    float* s_invnx = (float*)smbase;          // 128 floats
    float* s_sp    = s_invnx + BM;            // 128 floats
    float* s_invnm = s_sp + BM;               // 256 floats
    char*  smA_p   = smbase + SMALL_B;
    const uint32_t smA = smem_u32(smA_p);
    const uint32_t smB = smA + A_BYTES;
    // reduction arrays alias the B ring (dead after the main loop):
    float* s_red     = (float*)(smA_p + A_BYTES);   // 4*128 floats
    float* s_rowloss = s_red + 4 * BM;              // 128 floats
    float* s_part    = s_rowloss + BM;              // 8 floats

    const int tid  = threadIdx.x;
    const int blk  = blockIdx.x;
    const int w5   = tid >> 5, lane = tid & 31;
    const int wm   = w5 & 1;        // rows wm*64
    const int wn   = w5 >> 1;       // cols wn*64
    const int lq   = lane >> 3, l7 = lane & 7;

    if (tid < BM) {
        s_invnx[tid] = g_invnx[blk * BM + tid];
        s_sp[tid]    = g_sp[blk * BM + tid];
    }

    // ---- chunk loader: B chunk gg (32KB); for gg<8 also A chunk gg (16KB) ----
    const __nv_bfloat16* Asrc = g_Abf + (size_t)blk * BM * D_DIM;
    auto load_AB = [&](int gg) {
        const uint32_t slot = smB + (uint32_t)(gg % NBUF) * B_CHUNK_B;
        const __nv_bfloat16* bsrc =
            g_Bbf + (size_t)((gg >> 3) * NT) * D_DIM + (gg & 7) * KC;
        #pragma unroll
        for (int it = 0; it < 8; it++) {
            const int i = tid + it * NTHREADS;     // 0..2047
            const int r = i >> 3, s = i & 7;
            cp_async16(slot + (uint32_t)(r << 7) + (uint32_t)(((s ^ (r & 7)) & 7) << 4),
                       bsrc + (size_t)r * D_DIM + s * 8);
        }
        if (gg < 8) {
            #pragma unroll
            for (int it = 0; it < 4; it++) {
                const int i = tid + it * NTHREADS;  // 0..1023
                const int r = i >> 3, s = i & 7;
                cp_async16(smA + (uint32_t)gg * 16384u + (uint32_t)(r << 7) +
                               (uint32_t)(((s ^ (r & 7)) & 7) << 4),
                           Asrc + (size_t)r * D_DIM + gg * KC + s * 8);
            }
        }
        cp_commit();
    };

    load_AB(0); load_AB(1);

    const float wp = log1pf(expf(wptr[0]));
    __syncthreads();   // s_invnx/s_sp visible

    // per-thread row constants: (mt 0..3, h 0..1) -> 8 rows
    float inxr[4][2], spr[4][2];
    int   jrr[4][2];
    #pragma unroll
    for (int mt = 0; mt < 4; mt++)
        #pragma unroll
        for (int h = 0; h < 2; h++) {
            const int rl = wm * 64 + mt * 16 + h * 8 + (lane >> 2);
            inxr[mt][h] = s_invnx[rl];
            spr[mt][h]  = s_sp[rl];
            jrr[mt][h]  = blk * 8 + (rl >> 4);
        }

    float acc[4][8][4];   // [mt][n8 group][frag] = 128 regs
    #pragma unroll
    for (int mt = 0; mt < 4; mt++)
        #pragma unroll
        for (int p = 0; p < 8; p++)
            #pragma unroll
            for (int e = 0; e < 4; e++) acc[mt][p][e] = 0.f;

    float es[4][2];
    #pragma unroll
    for (int mt = 0; mt < 4; mt++) { es[mt][0] = 0.f; es[mt][1] = 0.f; }

    // ---- MMA over one resident chunk (warp tile 64 rows x 64 cols) ----
    auto mma_chunk = [&](int kcA, int slot) {
        const uint32_t Ac = smA + (uint32_t)kcA * 16384u;
        const uint32_t Bs = smB + (uint32_t)slot * B_CHUNK_B;
        #pragma unroll
        for (int k16 = 0; k16 < 4; k16++) {
            uint32_t a[4][4];
            #pragma unroll
            for (int mt = 0; mt < 4; mt++)
                ldsm4(a[mt], sw_addr(Ac, wm * 64 + mt * 16 + (lq & 1) * 8 + l7,
                                     k16 * 2 + (lq >> 1)));
            uint32_t b[4][4];
            #pragma unroll
            for (int p2 = 0; p2 < 4; p2++)
                ldsm4(b[p2], sw_addr(Bs, wn * 64 + p2 * 16 + (lq >> 1) * 8 + l7,
                                     k16 * 2 + (lq & 1)));
            #pragma unroll
            for (int p2 = 0; p2 < 4; p2++)
                #pragma unroll
                for (int mt = 0; mt < 4; mt++) {
                    mma16816(acc[mt][p2 * 2],     a[mt], b[p2][0], b[p2][1]);
                    mma16816(acc[mt][p2 * 2 + 1], a[mt], b[p2][2], b[p2][3]);
                }
        }
    };

    // ---- epilogue of tile t: normalize, diagonal swap, exp-accumulate ----
    auto epi_tile = [&](int t) {
        #pragma unroll
        for (int p = 0; p < 8; p++) {
            const int c0  = wn * 64 + p * 8 + (lane & 3) * 2;
            const float nm0 = s_invnm[c0];
            const float nm1 = s_invnm[c0 + 1];
            const int gc0 = t * NT + c0;
            #pragma unroll
            for (int mt = 0; mt < 4; mt++)
                #pragma unroll
                for (int h = 0; h < 2; h++) {
                    float s0 = acc[mt][p][h * 2 + 0] * inxr[mt][h] * nm0;
                    float s1 = acc[mt][p][h * 2 + 1] * inxr[mt][h] * nm1;
                    if (gc0     == jrr[mt][h]) s0 = spr[mt][h];
                    if (gc0 + 1 == jrr[mt][h]) s1 = spr[mt][h];
                    es[mt][h] += __expf(wp * s0) + __expf(wp * s1);
                    acc[mt][p][h * 2 + 0] = 0.f;
                    acc[mt][p][h * 2 + 1] = 0.f;
                }
        }
    };

    // ---- main loop: 1 barrier per chunk, prefetch distance 2, ring 3 ----
    #pragma unroll 1
    for (int t = 0; t < NTILES; t++) {
        #pragma unroll
        for (int kc = 0; kc < 8; kc++) {
            const int g = t * 8 + kc;
            if (g < NC - 1) cp_wait<1>(); else cp_wait<0>();
            __syncthreads();            // chunk g visible; all warps done with g-1
            if (g + 2 < NC) load_AB(g + 2);
            if (kc == 0 && tid < NT) s_invnm[tid] = g_invnm[t * NT + tid];
            mma_chunk(kc, g % NBUF);
        }
        epi_tile(t);   // s_invnm[t] stable: next overwrite is behind a barrier
    }

    __syncthreads();   // close last ldsm reads of the B ring before aliasing it

    // ---- reduce exp-sums: 4 lanes per row, then the four wn quarters ----
    #pragma unroll
    for (int mt = 0; mt < 4; mt++)
        #pragma unroll
        for (int h = 0; h < 2; h++) {
            float v = es[mt][h];
            v += __shfl_xor_sync(0xffffffffu, v, 1);
            v += __shfl_xor_sync(0xffffffffu, v, 2);
            if ((lane & 3) == 0)
                s_red[wn * BM + wm * 64 + mt * 16 + h * 8 + (lane >> 2)] = v;
        }
    __syncthreads();
    if (tid < BM) {
        const float tot = s_red[tid] + s_red[BM + tid] + s_red[2 * BM + tid] + s_red[3 * BM + tid];
        s_rowloss[tid] = logf(tot) - wp * s_sp[tid];
    }
    __syncthreads();
    if (tid < 8) {
        float t = 0.f;
        #pragma unroll
        for (int r = 0; r < 16; r++) t += s_rowloss[tid * 16 + r];
        s_part[tid] = t;
    }
    __syncthreads();
    if (tid == 0) {
        float t = 0.f;
        #pragma unroll
        for (int i = 0; i < 8; i++) t += s_part[i];
        atomicAdd(out, t * (1.f / (float)NROWS));
    }
}

extern "C" void kernel_launch(void* const* d_in, const int* in_sizes, int n_in,
                              void* d_out, int out_size)
{
    const float* x = (const float*)d_in[0];
    const float* w = (const float*)d_in[1];
    // b cancels: lse(wp*sim + b) - (wp*sim_pos + b) is b-independent.
    float* out = (float*)d_out;

    cudaFuncSetAttribute(k2_gemm_lse, cudaFuncAttributeMaxDynamicSharedMemorySize, DYN_SMEM);

    k1_stats<<<C_CLUST, 256>>>(x, out);
    k2_gemm_lse<<<NROWS / BM, NTHREADS, DYN_SMEM>>>(w, out);
}

// round 9
// speedup vs baseline: 1.1948x; 1.0692x over previous
#include <cuda_runtime.h>
#include <cuda_bf16.h>
#include <math.h>
#include <stdint.h>

#define EPS 1e-8f

#define C_CLUST 1024
#define S_SAMP  16
#define D_DIM   512
#define NROWS   (C_CLUST * S_SAMP)   // 16384

// ---- k2 tiling ----
#define BM 128                  // rows per CTA
#define NT 256                  // N-tile (centroids per tile) -> 4 tiles
#define KC 64                   // K-chunk (bf16, 128B rows)
#define NTILES 4
#define NC 32                   // total chunks = 4 tiles * 8 k-chunks
#define NTHREADS 256
#define A_BYTES   (BM * D_DIM * 2)        // 131072 (8 chunks x 16KB)
#define B_CHUNK_B (NT * KC * 2)           // 32768
#define NBUF 3                            // B ring depth
#define SMALL_B   2048
#define DYN_SMEM  (SMALL_B + A_BYTES + NBUF * B_CHUNK_B + 128)   // 231552 <= 232448

// ---------------------------------------------------------------------------
// Scratch (static device globals)
// ---------------------------------------------------------------------------
__device__ __nv_bfloat16 g_Abf[NROWS * D_DIM];    // 16 MB
__device__ __nv_bfloat16 g_Bbf[C_CLUST * D_DIM];  // 1 MB (mean centroids [k][d])
__device__ float g_invnm[C_CLUST];
__device__ float g_invnx[NROWS];
__device__ float g_sp[NROWS];                     // sim_pos (exact fp32)

// ---------------------------------------------------------------------------
// helpers
// ---------------------------------------------------------------------------
__device__ __forceinline__ uint32_t smem_u32(const void* p) {
    uint32_t a;
    asm("{ .reg .u64 t; cvta.to.shared.u64 t, %1; cvt.u32.u64 %0, t; }" : "=r"(a) : "l"(p));
    return a;
}
__device__ __forceinline__ void cp_async16(uint32_t dst, const void* src) {
    asm volatile("cp.async.cg.shared.global [%0], [%1], 16;\n" :: "r"(dst), "l"(src) : "memory");
}
__device__ __forceinline__ void cp_commit() {
    asm volatile("cp.async.commit_group;\n" ::: "memory");
}
template <int N> __device__ __forceinline__ void cp_wait() {
    asm volatile("cp.async.wait_group %0;\n" :: "n"(N) : "memory");
}
__device__ __forceinline__ void bar_pair(int id) {
    asm volatile("bar.sync %0, %1;" :: "r"(id), "r"(64u) : "memory");
}
__device__ __forceinline__ void ldsm4(uint32_t* r, uint32_t addr) {
    asm volatile("ldmatrix.sync.aligned.m8n8.x4.shared.b16 {%0,%1,%2,%3}, [%4];"
                 : "=r"(r[0]), "=r"(r[1]), "=r"(r[2]), "=r"(r[3]) : "r"(addr));
}
__device__ __forceinline__ void mma16816(float* c, const uint32_t* a, uint32_t b0, uint32_t b1) {
    asm volatile("mma.sync.aligned.m16n8k16.row.col.f32.bf16.bf16.f32 "
                 "{%0,%1,%2,%3}, {%4,%5,%6,%7}, {%8,%9}, {%0,%1,%2,%3};"
                 : "+f"(c[0]), "+f"(c[1]), "+f"(c[2]), "+f"(c[3])
                 : "r"(a[0]), "r"(a[1]), "r"(a[2]), "r"(a[3]), "r"(b0), "r"(b1));
}
// swizzled address inside a [rows][64 bf16] tile (128B rows)
__device__ __forceinline__ uint32_t sw_addr(uint32_t base, int row, int kseg) {
    return base + (uint32_t)(row << 7) + (uint32_t)(((kseg ^ (row & 7)) & 7) << 4);
}

// ---------------------------------------------------------------------------
// Kernel 1: per-cluster stats + bf16 conversion (A rows, B centroids).
// ---------------------------------------------------------------------------
__global__ void __launch_bounds__(256) k1_stats(const float* __restrict__ x,
                                                float* __restrict__ out)
{
    __shared__ float xs[S_SAMP * D_DIM];   // 32 KB
    __shared__ float ssum[D_DIM];
    __shared__ float sred[8];
    __shared__ float s_sumsq;

    const int j   = blockIdx.x;
    const int tid = threadIdx.x;

    if (j == 0 && tid == 0) out[0] = 0.f;   // k2 accumulates into out

    // Load + convert in one pass
    const float4* gx = (const float4*)(x + (size_t)j * S_SAMP * D_DIM);
    float4* xs4 = (float4*)xs;
    #pragma unroll
    for (int it = 0; it < 8; it++) {
        const int i4 = tid + it * 256;
        const float4 v = gx[i4];
        xs4[i4] = v;
        unsigned short h0 = __bfloat16_as_ushort(__float2bfloat16(v.x));
        unsigned short h1 = __bfloat16_as_ushort(__float2bfloat16(v.y));
        unsigned short h2 = __bfloat16_as_ushort(__float2bfloat16(v.z));
        unsigned short h3 = __bfloat16_as_ushort(__float2bfloat16(v.w));
        ((uint2*)g_Abf)[(size_t)j * 2048 + i4] =
            make_uint2(((uint32_t)h1 << 16) | h0, ((uint32_t)h3 << 16) | h2);
    }
    __syncthreads();

    // column sums over S
    const int d0 = tid, d1 = tid + 256;
    float s0 = 0.f, s1 = 0.f;
    #pragma unroll
    for (int i = 0; i < S_SAMP; i++) {
        s0 += xs[i * D_DIM + d0];
        s1 += xs[i * D_DIM + d1];
    }
    ssum[d0] = s0;
    ssum[d1] = s1;
    g_Bbf[(size_t)j * D_DIM + d0] = __float2bfloat16(s0 * (1.f / 16.f));
    g_Bbf[(size_t)j * D_DIM + d1] = __float2bfloat16(s1 * (1.f / 16.f));

    float p = s0 * s0 + s1 * s1;
    #pragma unroll
    for (int off = 16; off; off >>= 1) p += __shfl_down_sync(0xffffffffu, p, off);
    if ((tid & 31) == 0) sred[tid >> 5] = p;
    __syncthreads();
    if (tid == 0) {
        float t = 0.f;
        #pragma unroll
        for (int wi = 0; wi < 8; wi++) t += sred[wi];
        s_sumsq = t;
        g_invnm[j] = 16.f / sqrtf(t);
    }
    __syncthreads();
    const float sumsq = s_sumsq;

    const int w = tid >> 5, l = tid & 31;
    #pragma unroll
    for (int rr = 0; rr < 2; rr++) {
        const int i = w + rr * 8;
        float nx2 = 0.f, dt = 0.f;
        #pragma unroll
        for (int c = 0; c < 16; c++) {
            const int d = l + c * 32;
            const float a = xs[i * D_DIM + d];
            nx2 += a * a;
            dt  += a * ssum[d];
        }
        #pragma unroll
        for (int off = 16; off; off >>= 1) {
            nx2 += __shfl_down_sync(0xffffffffu, nx2, off);
            dt  += __shfl_down_sync(0xffffffffu, dt,  off);
        }
        if (l == 0) {
            const float loo_dot = (dt - nx2) * (1.f / 15.f);
            const float nloo2   = fmaxf((sumsq - 2.f * dt + nx2) * (1.f / 225.f), 0.f);
            const float nx      = sqrtf(nx2);
            g_invnx[j * S_SAMP + i] = 1.f / nx;
            g_sp[j * S_SAMP + i]    = loo_dot / fmaxf(nx * sqrtf(nloo2), EPS);
        }
    }
}

// ---------------------------------------------------------------------------
// Kernel 2: bf16 mma.sync GEMM + fused logsumexp, PAIRWISE pipeline.
// 128 CTAs x 256 threads, 8 warps, warp tile 64x64 (wm=warp&1, wn=warp>>1).
// Pair {2wn, 2wn+1} owns rows [wn*64, wn*64+64) of every B chunk slot:
// it loads ONLY those rows and reads ONLY those rows -> sync via named
// barrier of 64 threads (id wn+1). No full-CTA barrier in the main loop.
// ---------------------------------------------------------------------------
__global__ void __launch_bounds__(NTHREADS, 1) k2_gemm_lse(const float* __restrict__ wptr,
                                                           float* __restrict__ out)
{
    extern __shared__ char rawsm[];
    char* smbase = (char*)(((uintptr_t)rawsm + 127u) & ~(uintptr_t)127u);

    float* s_invnx = (float*)smbase;          // 128 floats
    float* s_sp    = s_invnx + BM;            // 128 floats
    float* s_invnm = s_sp + BM;               // 256 floats (pair-partitioned)
    char*  smA_p   = smbase + SMALL_B;
    const uint32_t smA = smem_u32(smA_p);
    const uint32_t smB = smA + A_BYTES;
    // reduction arrays alias the B ring (dead after the main loop):
    float* s_red     = (float*)(smA_p + A_BYTES);   // 4*128 floats
    float* s_rowloss = s_red + 4 * BM;              // 128 floats
    float* s_part    = s_rowloss + BM;              // 8 floats

    const int tid  = threadIdx.x;
    const int blk  = blockIdx.x;
    const int w5   = tid >> 5, lane = tid & 31;
    const int wm   = w5 & 1;        // rows wm*64
    const int wn   = w5 >> 1;       // cols wn*64, pair id
    const int pt   = wm * 32 + lane;      // 0..63 within pair
    const int lq   = lane >> 3, l7 = lane & 7;

    if (tid < BM) {
        s_invnx[tid] = g_invnx[blk * BM + tid];
        s_sp[tid]    = g_sp[blk * BM + tid];
    }

    // ---- A prologue: 8 chunks x 16KB, one cp.async group ----
    const __nv_bfloat16* Asrc = g_Abf + (size_t)blk * BM * D_DIM;
    #pragma unroll
    for (int kc = 0; kc < 8; kc++) {
        #pragma unroll
        for (int it = 0; it < 4; it++) {
            const int i = tid + it * NTHREADS;   // 0..1023
            const int r = i >> 3, s = i & 7;
            cp_async16(smA + (uint32_t)kc * 16384u + (uint32_t)(r << 7) +
                           (uint32_t)(((s ^ (r & 7)) & 7) << 4),
                       Asrc + (size_t)r * D_DIM + kc * KC + s * 8);
        }
    }
    cp_commit();

    // ---- per-pair B chunk loader: 64 rows x 8 segs, 8 cp.async per thread ----
    auto load_B_pair = [&](int gg) {
        const uint32_t slot = smB + (uint32_t)(gg % NBUF) * B_CHUNK_B;
        const __nv_bfloat16* bsrc =
            g_Bbf + (size_t)((gg >> 3) * NT + wn * 64) * D_DIM + (gg & 7) * KC;
        #pragma unroll
        for (int it = 0; it < 8; it++) {
            const int i = pt + it * 64;          // 0..511
            const int r = i >> 3, s = i & 7;     // r 0..63
            const int row = wn * 64 + r;         // absolute row in slot
            cp_async16(slot + (uint32_t)(row << 7) +
                           (uint32_t)(((s ^ (row & 7)) & 7) << 4),
                       bsrc + (size_t)r * D_DIM + s * 8);
        }
        cp_commit();
    };

    load_B_pair(0);
    load_B_pair(1);

    const float wp = log1pf(expf(wptr[0]));

    cp_wait<1>();      // A + B0 complete (own thread); B1 may be in flight
    __syncthreads();   // A, B0, s_invnx/s_sp visible to all

    // per-thread row constants: (mt 0..3, h 0..1) -> 8 rows
    float inxr[4][2], spr[4][2];
    int   jrr[4][2];
    #pragma unroll
    for (int mt = 0; mt < 4; mt++)
        #pragma unroll
        for (int h = 0; h < 2; h++) {
            const int rl = wm * 64 + mt * 16 + h * 8 + (lane >> 2);
            inxr[mt][h] = s_invnx[rl];
            spr[mt][h]  = s_sp[rl];
            jrr[mt][h]  = blk * 8 + (rl >> 4);
        }

    float acc[4][8][4];   // 128 regs
    #pragma unroll
    for (int mt = 0; mt < 4; mt++)
        #pragma unroll
        for (int p = 0; p < 8; p++)
            #pragma unroll
            for (int e = 0; e < 4; e++) acc[mt][p][e] = 0.f;

    float es[4][2];
    #pragma unroll
    for (int mt = 0; mt < 4; mt++) { es[mt][0] = 0.f; es[mt][1] = 0.f; }

    // ---- MMA over one resident chunk (warp tile 64 rows x 64 cols) ----
    auto mma_chunk = [&](int kcA, int slot) {
        const uint32_t Ac = smA + (uint32_t)kcA * 16384u;
        const uint32_t Bs = smB + (uint32_t)slot * B_CHUNK_B;
        #pragma unroll
        for (int k16 = 0; k16 < 4; k16++) {
            uint32_t a[4][4];
            #pragma unroll
            for (int mt = 0; mt < 4; mt++)
                ldsm4(a[mt], sw_addr(Ac, wm * 64 + mt * 16 + (lq & 1) * 8 + l7,
                                     k16 * 2 + (lq >> 1)));
            uint32_t b[4][4];
            #pragma unroll
            for (int p2 = 0; p2 < 4; p2++)
                ldsm4(b[p2], sw_addr(Bs, wn * 64 + p2 * 16 + (lq >> 1) * 8 + l7,
                                     k16 * 2 + (lq & 1)));
            #pragma unroll
            for (int p2 = 0; p2 < 4; p2++)
                #pragma unroll
                for (int mt = 0; mt < 4; mt++) {
                    mma16816(acc[mt][p2 * 2],     a[mt], b[p2][0], b[p2][1]);
                    mma16816(acc[mt][p2 * 2 + 1], a[mt], b[p2][2], b[p2][3]);
                }
        }
    };

    // ---- epilogue of tile t ----
    auto epi_tile = [&](int t) {
        #pragma unroll
        for (int p = 0; p < 8; p++) {
            const int c0  = wn * 64 + p * 8 + (lane & 3) * 2;
            const float nm0 = s_invnm[c0];
            const float nm1 = s_invnm[c0 + 1];
            const int gc0 = t * NT + c0;
            #pragma unroll
            for (int mt = 0; mt < 4; mt++)
                #pragma unroll
                for (int h = 0; h < 2; h++) {
                    float s0 = acc[mt][p][h * 2 + 0] * inxr[mt][h] * nm0;
                    float s1 = acc[mt][p][h * 2 + 1] * inxr[mt][h] * nm1;
                    if (gc0     == jrr[mt][h]) s0 = spr[mt][h];
                    if (gc0 + 1 == jrr[mt][h]) s1 = spr[mt][h];
                    es[mt][h] += __expf(wp * s0) + __expf(wp * s1);
                    acc[mt][p][h * 2 + 0] = 0.f;
                    acc[mt][p][h * 2 + 1] = 0.f;
                }
        }
    };

    // ---- main loop: pairwise sync only ----
    #pragma unroll 1
    for (int t = 0; t < NTILES; t++) {
        #pragma unroll
        for (int kc = 0; kc < 8; kc++) {
            const int g = t * 8 + kc;
            if (g > 0) {
                if (g < NC - 1) cp_wait<1>(); else cp_wait<0>();
                bar_pair(wn + 1);      // pair's loads for chunk g visible;
                                        // both warps done reading chunk g-1
            }
            if (g + 2 < NC) load_B_pair(g + 2);
            if (kc == 0)
                s_invnm[wn * 64 + pt] = g_invnm[t * NT + wn * 64 + pt];
            mma_chunk(kc, g % NBUF);
        }
        epi_tile(t);   // invnm writes for tile t+1 are behind the kc==0 pair bar
    }

    __syncthreads();   // all pairs done; safe to alias B ring with s_red

    // ---- reduce exp-sums: 4 lanes per row, then the four wn quarters ----
    #pragma unroll
    for (int mt = 0; mt < 4; mt++)
        #pragma unroll
        for (int h = 0; h < 2; h++) {
            float v = es[mt][h];
            v += __shfl_xor_sync(0xffffffffu, v, 1);
            v += __shfl_xor_sync(0xffffffffu, v, 2);
            if ((lane & 3) == 0)
                s_red[wn * BM + wm * 64 + mt * 16 + h * 8 + (lane >> 2)] = v;
        }
    __syncthreads();
    if (tid < BM) {
        const float tot = s_red[tid] + s_red[BM + tid] + s_red[2 * BM + tid] + s_red[3 * BM + tid];
        s_rowloss[tid] = logf(tot) - wp * s_sp[tid];
    }
    __syncthreads();
    if (tid < 8) {
        float t = 0.f;
        #pragma unroll
        for (int r = 0; r < 16; r++) t += s_rowloss[tid * 16 + r];
        s_part[tid] = t;
    }
    __syncthreads();
    if (tid == 0) {
        float t = 0.f;
        #pragma unroll
        for (int i = 0; i < 8; i++) t += s_part[i];
        atomicAdd(out, t * (1.f / (float)NROWS));
    }
}

extern "C" void kernel_launch(void* const* d_in, const int* in_sizes, int n_in,
                              void* d_out, int out_size)
{
    const float* x = (const float*)d_in[0];
    const float* w = (const float*)d_in[1];
    // b cancels: lse(wp*sim + b) - (wp*sim_pos + b) is b-independent.
    float* out = (float*)d_out;

    cudaFuncSetAttribute(k2_gemm_lse, cudaFuncAttributeMaxDynamicSharedMemorySize, DYN_SMEM);

    k1_stats<<<C_CLUST, 256>>>(x, out);
    k2_gemm_lse<<<NROWS / BM, NTHREADS, DYN_SMEM>>>(w, out);
}

// round 10
// speedup vs baseline: 1.2083x; 1.0113x over previous
#include <cuda_runtime.h>
#include <cuda_bf16.h>
#include <math.h>
#include <stdint.h>

#define EPS 1e-8f

#define C_CLUST 1024
#define S_SAMP  16
#define D_DIM   512
#define NROWS   (C_CLUST * S_SAMP)   // 16384

// ---- k2 tiling ----
#define BM 128                  // rows per CTA
#define NT 256                  // N-tile -> 4 tiles
#define KC 64                   // K-chunk (bf16, 128B rows)
#define NTILES 4
#define NC 32                   // chunks = 4 tiles * 8
#define NTHREADS 512
#define A_BYTES   (BM * D_DIM * 2)        // 131072
#define B_CHUNK_B (NT * KC * 2)           // 32768
#define NBUF 3
#define SMALL_B   2048
#define DYN_SMEM  (SMALL_B + A_BYTES + NBUF * B_CHUNK_B + 128)   // 231552 <= 232448

// ---------------------------------------------------------------------------
// Scratch (static device globals)
// ---------------------------------------------------------------------------
__device__ __nv_bfloat16 g_Abf[NROWS * D_DIM];    // 16 MB
__device__ __nv_bfloat16 g_Bbf[C_CLUST * D_DIM];  // 1 MB (mean centroids [k][d])
__device__ float g_invnm[C_CLUST];
__device__ float g_invnx[NROWS];
__device__ float g_sp[NROWS];                     // sim_pos (exact fp32)

// ---------------------------------------------------------------------------
// helpers
// ---------------------------------------------------------------------------
__device__ __forceinline__ uint32_t smem_u32(const void* p) {
    uint32_t a;
    asm("{ .reg .u64 t; cvta.to.shared.u64 t, %1; cvt.u32.u64 %0, t; }" : "=r"(a) : "l"(p));
    return a;
}
__device__ __forceinline__ void cp_async16(uint32_t dst, const void* src) {
    asm volatile("cp.async.cg.shared.global [%0], [%1], 16;\n" :: "r"(dst), "l"(src) : "memory");
}
__device__ __forceinline__ void cp_commit() {
    asm volatile("cp.async.commit_group;\n" ::: "memory");
}
template <int N> __device__ __forceinline__ void cp_wait() {
    asm volatile("cp.async.wait_group %0;\n" :: "n"(N) : "memory");
}
__device__ __forceinline__ void bar_quad(int id) {
    asm volatile("bar.sync %0, %1;" :: "r"(id), "r"(128u) : "memory");
}
__device__ __forceinline__ void ldsm4(uint32_t* r, uint32_t addr) {
    asm volatile("ldmatrix.sync.aligned.m8n8.x4.shared.b16 {%0,%1,%2,%3}, [%4];"
                 : "=r"(r[0]), "=r"(r[1]), "=r"(r[2]), "=r"(r[3]) : "r"(addr));
}
__device__ __forceinline__ void mma16816(float* c, const uint32_t* a, uint32_t b0, uint32_t b1) {
    asm volatile("mma.sync.aligned.m16n8k16.row.col.f32.bf16.bf16.f32 "
                 "{%0,%1,%2,%3}, {%4,%5,%6,%7}, {%8,%9}, {%0,%1,%2,%3};"
                 : "+f"(c[0]), "+f"(c[1]), "+f"(c[2]), "+f"(c[3])
                 : "r"(a[0]), "r"(a[1]), "r"(a[2]), "r"(a[3]), "r"(b0), "r"(b1));
}
// swizzled address inside a [rows][64 bf16] tile (128B rows)
__device__ __forceinline__ uint32_t sw_addr(uint32_t base, int row, int kseg) {
    return base + (uint32_t)(row << 7) + (uint32_t)(((kseg ^ (row & 7)) & 7) << 4);
}

// ---------------------------------------------------------------------------
// Kernel 1: per-cluster stats + bf16 conversion (A rows, B centroids).
// ---------------------------------------------------------------------------
__global__ void __launch_bounds__(256) k1_stats(const float* __restrict__ x,
                                                float* __restrict__ out)
{
    __shared__ float xs[S_SAMP * D_DIM];   // 32 KB
    __shared__ float ssum[D_DIM];
    __shared__ float sred[8];
    __shared__ float s_sumsq;

    const int j   = blockIdx.x;
    const int tid = threadIdx.x;

    if (j == 0 && tid == 0) out[0] = 0.f;   // k2 accumulates into out

    const float4* gx = (const float4*)(x + (size_t)j * S_SAMP * D_DIM);
    float4* xs4 = (float4*)xs;
    #pragma unroll
    for (int it = 0; it < 8; it++) {
        const int i4 = tid + it * 256;
        const float4 v = gx[i4];
        xs4[i4] = v;
        unsigned short h0 = __bfloat16_as_ushort(__float2bfloat16(v.x));
        unsigned short h1 = __bfloat16_as_ushort(__float2bfloat16(v.y));
        unsigned short h2 = __bfloat16_as_ushort(__float2bfloat16(v.z));
        unsigned short h3 = __bfloat16_as_ushort(__float2bfloat16(v.w));
        ((uint2*)g_Abf)[(size_t)j * 2048 + i4] =
            make_uint2(((uint32_t)h1 << 16) | h0, ((uint32_t)h3 << 16) | h2);
    }
    __syncthreads();

    const int d0 = tid, d1 = tid + 256;
    float s0 = 0.f, s1 = 0.f;
    #pragma unroll
    for (int i = 0; i < S_SAMP; i++) {
        s0 += xs[i * D_DIM + d0];
        s1 += xs[i * D_DIM + d1];
    }
    ssum[d0] = s0;
    ssum[d1] = s1;
    g_Bbf[(size_t)j * D_DIM + d0] = __float2bfloat16(s0 * (1.f / 16.f));
    g_Bbf[(size_t)j * D_DIM + d1] = __float2bfloat16(s1 * (1.f / 16.f));

    float p = s0 * s0 + s1 * s1;
    #pragma unroll
    for (int off = 16; off; off >>= 1) p += __shfl_down_sync(0xffffffffu, p, off);
    if ((tid & 31) == 0) sred[tid >> 5] = p;
    __syncthreads();
    if (tid == 0) {
        float t = 0.f;
        #pragma unroll
        for (int wi = 0; wi < 8; wi++) t += sred[wi];
        s_sumsq = t;
        g_invnm[j] = 16.f / sqrtf(t);
    }
    __syncthreads();
    const float sumsq = s_sumsq;

    const int w = tid >> 5, l = tid & 31;
    #pragma unroll
    for (int rr = 0; rr < 2; rr++) {
        const int i = w + rr * 8;
        float nx2 = 0.f, dt = 0.f;
        #pragma unroll
        for (int c = 0; c < 16; c++) {
            const int d = l + c * 32;
            const float a = xs[i * D_DIM + d];
            nx2 += a * a;
            dt  += a * ssum[d];
        }
        #pragma unroll
        for (int off = 16; off; off >>= 1) {
            nx2 += __shfl_down_sync(0xffffffffu, nx2, off);
            dt  += __shfl_down_sync(0xffffffffu, dt,  off);
        }
        if (l == 0) {
            const float loo_dot = (dt - nx2) * (1.f / 15.f);
            const float nloo2   = fmaxf((sumsq - 2.f * dt + nx2) * (1.f / 225.f), 0.f);
            const float nx      = sqrtf(nx2);
            g_invnx[j * S_SAMP + i] = 1.f / nx;
            g_sp[j * S_SAMP + i]    = loo_dot / fmaxf(nx * sqrtf(nloo2), EPS);
        }
    }
}

// ---------------------------------------------------------------------------
// Kernel 2: bf16 mma.sync GEMM + fused logsumexp, QUAD pipeline.
// 128 CTAs x 512 threads, 16 warps, warp tile 32x64:
//   wm = wid&3  -> rows wm*32 (also the SMSP id)
//   wn = wid>>2 -> cols wn*64, quad id (tids 128*wn .. +127)
// Quad wn loads/reads only rows [wn*64, wn*64+64) of each B slot; syncs with
// bar.sync(wn+1, 128). Each SMSP hosts one warp from each of the 4 quads.
// ---------------------------------------------------------------------------
__global__ void __launch_bounds__(NTHREADS, 1) k2_gemm_lse(const float* __restrict__ wptr,
                                                           float* __restrict__ out)
{
    extern __shared__ char rawsm[];
    char* smbase = (char*)(((uintptr_t)rawsm + 127u) & ~(uintptr_t)127u);

    float* s_invnx = (float*)smbase;          // 128 floats
    float* s_sp    = s_invnx + BM;            // 128 floats
    float* s_invnm = s_sp + BM;               // 256 floats (quad-partitioned)
    char*  smA_p   = smbase + SMALL_B;
    const uint32_t smA = smem_u32(smA_p);
    const uint32_t smB = smA + A_BYTES;
    // reduction arrays alias the B ring (dead after the main loop):
    float* s_red     = (float*)(smA_p + A_BYTES);   // 4*128 floats
    float* s_rowloss = s_red + 4 * BM;              // 128 floats
    float* s_part    = s_rowloss + BM;              // 8 floats

    const int tid  = threadIdx.x;
    const int blk  = blockIdx.x;
    const int w5   = tid >> 5, lane = tid & 31;
    const int wm   = w5 & 3;        // rows wm*32, SMSP id
    const int wn   = w5 >> 2;       // cols wn*64, quad id
    const int qt   = tid & 127;     // 0..127 within quad
    const int lq   = lane >> 3, l7 = lane & 7;

    if (tid < BM) {
        s_invnx[tid] = g_invnx[blk * BM + tid];
        s_sp[tid]    = g_sp[blk * BM + tid];
    }

    // ---- A prologue: 8 chunks x 16KB, one cp.async group (all 512 threads) ----
    const __nv_bfloat16* Asrc = g_Abf + (size_t)blk * BM * D_DIM;
    #pragma unroll
    for (int kc = 0; kc < 8; kc++) {
        #pragma unroll
        for (int it = 0; it < 2; it++) {
            const int i = tid + it * NTHREADS;   // 0..1023
            const int r = i >> 3, s = i & 7;
            cp_async16(smA + (uint32_t)kc * 16384u + (uint32_t)(r << 7) +
                           (uint32_t)(((s ^ (r & 7)) & 7) << 4),
                       Asrc + (size_t)r * D_DIM + kc * KC + s * 8);
        }
    }
    cp_commit();

    // ---- per-quad B chunk loader: 64 rows x 8 segs, 4 cp.async per thread ----
    auto load_B_quad = [&](int gg) {
        const uint32_t slot = smB + (uint32_t)(gg % NBUF) * B_CHUNK_B;
        const __nv_bfloat16* bsrc =
            g_Bbf + (size_t)((gg >> 3) * NT + wn * 64) * D_DIM + (gg & 7) * KC;
        #pragma unroll
        for (int it = 0; it < 4; it++) {
            const int i = qt + it * 128;         // 0..511
            const int r = i >> 3, s = i & 7;     // r 0..63
            const int row = wn * 64 + r;
            cp_async16(slot + (uint32_t)(row << 7) +
                           (uint32_t)(((s ^ (row & 7)) & 7) << 4),
                       bsrc + (size_t)r * D_DIM + s * 8);
        }
        cp_commit();
    };

    load_B_quad(0);
    load_B_quad(1);

    const float wp = log1pf(expf(wptr[0]));

    cp_wait<1>();      // A + B0 complete; B1 may be in flight
    __syncthreads();   // A, B0, s_invnx/s_sp visible to all

    float acc[2][8][4];   // 64 regs: [mt][n8 group][frag]
    #pragma unroll
    for (int mt = 0; mt < 2; mt++)
        #pragma unroll
        for (int p = 0; p < 8; p++)
            #pragma unroll
            for (int e = 0; e < 4; e++) acc[mt][p][e] = 0.f;

    float es[2][2] = {{0.f, 0.f}, {0.f, 0.f}};

    // ---- MMA over one resident chunk (warp tile 32 rows x 64 cols) ----
    auto mma_chunk = [&](int kcA, int slot) {
        const uint32_t Ac = smA + (uint32_t)kcA * 16384u;
        const uint32_t Bs = smB + (uint32_t)slot * B_CHUNK_B;
        #pragma unroll
        for (int k16 = 0; k16 < 4; k16++) {
            uint32_t a[2][4];
            #pragma unroll
            for (int mt = 0; mt < 2; mt++)
                ldsm4(a[mt], sw_addr(Ac, wm * 32 + mt * 16 + (lq & 1) * 8 + l7,
                                     k16 * 2 + (lq >> 1)));
            uint32_t b[4][4];
            #pragma unroll
            for (int p2 = 0; p2 < 4; p2++)
                ldsm4(b[p2], sw_addr(Bs, wn * 64 + p2 * 16 + (lq >> 1) * 8 + l7,
                                     k16 * 2 + (lq & 1)));
            #pragma unroll
            for (int p2 = 0; p2 < 4; p2++)
                #pragma unroll
                for (int mt = 0; mt < 2; mt++) {
                    mma16816(acc[mt][p2 * 2],     a[mt], b[p2][0], b[p2][1]);
                    mma16816(acc[mt][p2 * 2 + 1], a[mt], b[p2][2], b[p2][3]);
                }
        }
    };

    // ---- epilogue of tile t (cold path; row constants read from smem) ----
    auto epi_tile = [&](int t) {
        #pragma unroll
        for (int mt = 0; mt < 2; mt++)
            #pragma unroll
            for (int h = 0; h < 2; h++) {
                const int rl = wm * 32 + mt * 16 + h * 8 + (lane >> 2);
                const float inx = s_invnx[rl];
                const float spv = s_sp[rl];
                const int   jr  = blk * 8 + (rl >> 4);
                #pragma unroll
                for (int p = 0; p < 8; p++) {
                    const int c0  = wn * 64 + p * 8 + (lane & 3) * 2;
                    const int gc0 = t * NT + c0;
                    float s0 = acc[mt][p][h * 2 + 0] * inx * s_invnm[c0];
                    float s1 = acc[mt][p][h * 2 + 1] * inx * s_invnm[c0 + 1];
                    if (gc0     == jr) s0 = spv;
                    if (gc0 + 1 == jr) s1 = spv;
                    es[mt][h] += __expf(wp * s0) + __expf(wp * s1);
                    acc[mt][p][h * 2 + 0] = 0.f;
                    acc[mt][p][h * 2 + 1] = 0.f;
                }
            }
    };

    // ---- main loop: quad-level sync only ----
    #pragma unroll 1
    for (int t = 0; t < NTILES; t++) {
        #pragma unroll
        for (int kc = 0; kc < 8; kc++) {
            const int g = t * 8 + kc;
            if (g > 0) {
                if (g < NC - 1) cp_wait<1>(); else cp_wait<0>();
                bar_quad(wn + 1);      // quad's loads for chunk g visible;
                                        // all 4 warps done reading chunk g-1
            }
            if (g + 2 < NC) load_B_quad(g + 2);
            if (kc == 0 && qt < 64)
                s_invnm[wn * 64 + qt] = g_invnm[t * NT + wn * 64 + qt];
            mma_chunk(kc, g % NBUF);
        }
        epi_tile(t);   // invnm writes for tile t+1 are behind the kc==0 quad bar
    }

    __syncthreads();   // all quads done; safe to alias B ring with s_red

    // ---- reduce exp-sums: 4 lanes per row, then the four wn quarters ----
    #pragma unroll
    for (int mt = 0; mt < 2; mt++)
        #pragma unroll
        for (int h = 0; h < 2; h++) {
            float v = es[mt][h];
            v += __shfl_xor_sync(0xffffffffu, v, 1);
            v += __shfl_xor_sync(0xffffffffu, v, 2);
            if ((lane & 3) == 0)
                s_red[wn * BM + wm * 32 + mt * 16 + h * 8 + (lane >> 2)] = v;
        }
    __syncthreads();
    if (tid < BM) {
        const float tot = s_red[tid] + s_red[BM + tid] + s_red[2 * BM + tid] + s_red[3 * BM + tid];
        s_rowloss[tid] = logf(tot) - wp * s_sp[tid];
    }
    __syncthreads();
    if (tid < 8) {
        float t = 0.f;
        #pragma unroll
        for (int r = 0; r < 16; r++) t += s_rowloss[tid * 16 + r];
        s_part[tid] = t;
    }
    __syncthreads();
    if (tid == 0) {
        float t = 0.f;
        #pragma unroll
        for (int i = 0; i < 8; i++) t += s_part[i];
        atomicAdd(out, t * (1.f / (float)NROWS));
    }
}

extern "C" void kernel_launch(void* const* d_in, const int* in_sizes, int n_in,
                              void* d_out, int out_size)
{
    const float* x = (const float*)d_in[0];
    const float* w = (const float*)d_in[1];
    // b cancels: lse(wp*sim + b) - (wp*sim_pos + b) is b-independent.
    float* out = (float*)d_out;

    cudaFuncSetAttribute(k2_gemm_lse, cudaFuncAttributeMaxDynamicSharedMemorySize, DYN_SMEM);

    k1_stats<<<C_CLUST, 256>>>(x, out);
    k2_gemm_lse<<<NROWS / BM, NTHREADS, DYN_SMEM>>>(w, out);
}

// round 12
// speedup vs baseline: 1.2836x; 1.0623x over previous
#include <cuda_runtime.h>
#include <cuda_bf16.h>
#include <math.h>
#include <stdint.h>

#define EPS 1e-8f

#define C_CLUST 1024
#define S_SAMP  16
#define D_DIM   512
#define NROWS   (C_CLUST * S_SAMP)   // 16384

// ---- k2 tiling ----
#define NCTA 148                // persistent-ish grid: 136x7 + 12x6 m16-units
#define NT 256                  // N-tile -> 4 tiles
#define KC 64                   // K-chunk
#define NTILES 4
#define NC 32                   // chunks
#define NTHREADS 256
#define MAXMT 7                 // max m16 units per CTA (112 rows)
#define A_CH_B   (MAXMT * 16 * 128)       // 14336 per K-chunk
#define A_BYTES  (8 * A_CH_B)             // 114688
#define B_CHUNK_B (NT * KC * 2)           // 32768
#define NBUF 3
#define SMALL_B  1024
#define DYN_SMEM (SMALL_B + A_BYTES + NBUF * B_CHUNK_B + 256)  // 214272 <= 232448

// ---------------------------------------------------------------------------
// Scratch (static device globals)
// ---------------------------------------------------------------------------
__device__ __nv_bfloat16 g_Abf[NROWS * D_DIM];    // 16 MB
__device__ __nv_bfloat16 g_Bbf[C_CLUST * D_DIM];  // 1 MB (mean centroids [k][d])
__device__ float g_invnm[C_CLUST];
__device__ float g_invnx[NROWS];
__device__ float g_sp[NROWS];                     // sim_pos (exact fp32)

// ---------------------------------------------------------------------------
// helpers
// ---------------------------------------------------------------------------
__device__ __forceinline__ uint32_t smem_u32(const void* p) {
    uint32_t a;
    asm("{ .reg .u64 t; cvta.to.shared.u64 t, %1; cvt.u32.u64 %0, t; }" : "=r"(a) : "l"(p));
    return a;
}
__device__ __forceinline__ void cp_async16(uint32_t dst, const void* src) {
    asm volatile("cp.async.cg.shared.global [%0], [%1], 16;\n" :: "r"(dst), "l"(src) : "memory");
}
__device__ __forceinline__ void cp_commit() {
    asm volatile("cp.async.commit_group;\n" ::: "memory");
}
template <int N> __device__ __forceinline__ void cp_wait() {
    asm volatile("cp.async.wait_group %0;\n" :: "n"(N) : "memory");
}
__device__ __forceinline__ void ldsm4(uint32_t* r, uint32_t addr) {
    asm volatile("ldmatrix.sync.aligned.m8n8.x4.shared.b16 {%0,%1,%2,%3}, [%4];"
                 : "=r"(r[0]), "=r"(r[1]), "=r"(r[2]), "=r"(r[3]) : "r"(addr));
}
__device__ __forceinline__ void mma16816(float* c, const uint32_t* a, uint32_t b0, uint32_t b1) {
    asm volatile("mma.sync.aligned.m16n8k16.row.col.f32.bf16.bf16.f32 "
                 "{%0,%1,%2,%3}, {%4,%5,%6,%7}, {%8,%9}, {%0,%1,%2,%3};"
                 : "+f"(c[0]), "+f"(c[1]), "+f"(c[2]), "+f"(c[3])
                 : "r"(a[0]), "r"(a[1]), "r"(a[2]), "r"(a[3]), "r"(b0), "r"(b1));
}
// swizzled address inside a tile with 128B rows
__device__ __forceinline__ uint32_t sw_addr(uint32_t base, int row, int kseg) {
    return base + (uint32_t)(row << 7) + (uint32_t)(((kseg ^ (row & 7)) & 7) << 4);
}

// ---------------------------------------------------------------------------
// Kernel 1: per-cluster stats + bf16 conversion (A rows, B centroids).
// ---------------------------------------------------------------------------
__global__ void __launch_bounds__(256) k1_stats(const float* __restrict__ x,
                                                float* __restrict__ out)
{
    __shared__ float xs[S_SAMP * D_DIM];   // 32 KB
    __shared__ float ssum[D_DIM];
    __shared__ float sred[8];
    __shared__ float s_sumsq;

    const int j   = blockIdx.x;
    const int tid = threadIdx.x;

    if (j == 0 && tid == 0) out[0] = 0.f;   // k2 accumulates into out

    const float4* gx = (const float4*)(x + (size_t)j * S_SAMP * D_DIM);
    float4* xs4 = (float4*)xs;
    #pragma unroll
    for (int it = 0; it < 8; it++) {
        const int i4 = tid + it * 256;
        const float4 v = gx[i4];
        xs4[i4] = v;
        unsigned short h0 = __bfloat16_as_ushort(__float2bfloat16(v.x));
        unsigned short h1 = __bfloat16_as_ushort(__float2bfloat16(v.y));
        unsigned short h2 = __bfloat16_as_ushort(__float2bfloat16(v.z));
        unsigned short h3 = __bfloat16_as_ushort(__float2bfloat16(v.w));
        ((uint2*)g_Abf)[(size_t)j * 2048 + i4] =
            make_uint2(((uint32_t)h1 << 16) | h0, ((uint32_t)h3 << 16) | h2);
    }
    __syncthreads();

    const int d0 = tid, d1 = tid + 256;
    float s0 = 0.f, s1 = 0.f;
    #pragma unroll
    for (int i = 0; i < S_SAMP; i++) {
        s0 += xs[i * D_DIM + d0];
        s1 += xs[i * D_DIM + d1];
    }
    ssum[d0] = s0;
    ssum[d1] = s1;
    g_Bbf[(size_t)j * D_DIM + d0] = __float2bfloat16(s0 * (1.f / 16.f));
    g_Bbf[(size_t)j * D_DIM + d1] = __float2bfloat16(s1 * (1.f / 16.f));

    float p = s0 * s0 + s1 * s1;
    #pragma unroll
    for (int off = 16; off; off >>= 1) p += __shfl_down_sync(0xffffffffu, p, off);
    if ((tid & 31) == 0) sred[tid >> 5] = p;
    __syncthreads();
    if (tid == 0) {
        float t = 0.f;
        #pragma unroll
        for (int wi = 0; wi < 8; wi++) t += sred[wi];
        s_sumsq = t;
        g_invnm[j] = 16.f / sqrtf(t);
    }
    __syncthreads();
    const float sumsq = s_sumsq;

    const int w = tid >> 5, l = tid & 31;
    #pragma unroll
    for (int rr = 0; rr < 2; rr++) {
        const int i = w + rr * 8;
        float nx2 = 0.f, dt = 0.f;
        #pragma unroll
        for (int c = 0; c < 16; c++) {
            const int d = l + c * 32;
            const float a = xs[i * D_DIM + d];
            nx2 += a * a;
            dt  += a * ssum[d];
        }
        #pragma unroll
        for (int off = 16; off; off >>= 1) {
            nx2 += __shfl_down_sync(0xffffffffu, nx2, off);
            dt  += __shfl_down_sync(0xffffffffu, dt,  off);
        }
        if (l == 0) {
            const float loo_dot = (dt - nx2) * (1.f / 15.f);
            const float nloo2   = fmaxf((sumsq - 2.f * dt + nx2) * (1.f / 225.f), 0.f);
            const float nx      = sqrtf(nx2);
            g_invnx[j * S_SAMP + i] = 1.f / nx;
            g_sp[j * S_SAMP + i]    = loo_dot / fmaxf(nx * sqrtf(nloo2), EPS);
        }
    }
}

// ---------------------------------------------------------------------------
// Kernel 2: bf16 mma.sync GEMM + fused logsumexp, ZERO-BARRIER main loop.
// 148 CTAs x 256 threads. CTA c owns nmt m16-units (7 for c<136, else 6).
// 8 warps; warp wn owns output cols [wn*32, wn*32+32) of each N-tile and
// loads ONLY rows [wn*32, wn*32+32) of each B ring slot -> warp-private
// pipeline, synced by its own cp.async.wait_group + __syncwarp.
// ---------------------------------------------------------------------------
__global__ void __launch_bounds__(NTHREADS, 1) k2_gemm_lse(const float* __restrict__ wptr,
                                                           float* __restrict__ out)
{
    extern __shared__ char rawsm[];
    char* smbase = (char*)(((uintptr_t)rawsm + 127u) & ~(uintptr_t)127u);

    float* s_invnx = (float*)smbase;          // up to 112 floats
    float* s_sp    = s_invnx + 112;           // up to 112 floats
    char*  smA_p   = smbase + SMALL_B;
    const uint32_t smA = smem_u32(smA_p);
    const uint32_t smB = smA + A_BYTES;
    // final-reduction arrays alias the B ring (dead after the main loop):
    float* s_red     = (float*)(smA_p + A_BYTES);   // 8*112 floats
    float* s_rowloss = s_red + 8 * 112;             // 112 floats
    float* s_part    = s_rowloss + 112;             // 8 floats

    const int tid  = threadIdx.x;
    const int lane = tid & 31;
    const int wn   = tid >> 5;           // warp id = column-slice owner
    const int lq   = lane >> 3, l7 = lane & 7;

    const int c    = blockIdx.x;
    const int s16  = (c < 136) ? c * 7 : 952 + (c - 136) * 6;  // first m16 unit
    const int nmt  = (c < 136) ? 7 : 6;
    const int nr   = nmt * 16;

    if (tid < nr) {
        s_invnx[tid] = g_invnx[s16 * 16 + tid];
        s_sp[tid]    = g_sp[s16 * 16 + tid];
    }

    // ---- A prologue: nr rows x 512 cols, 8 chunks, one cp.async group ----
    const __nv_bfloat16* Asrc = g_Abf + (size_t)s16 * 16 * D_DIM;
    #pragma unroll 1
    for (int kc = 0; kc < 8; kc++) {
        for (int i = tid; i < nr * 8; i += NTHREADS) {
            const int r = i >> 3, s = i & 7;
            cp_async16(smA + (uint32_t)kc * A_CH_B + (uint32_t)(r << 7) +
                           (uint32_t)(((s ^ (r & 7)) & 7) << 4),
                       Asrc + (size_t)r * D_DIM + kc * KC + s * 8);
        }
    }
    cp_commit();

    // ---- warp-private B chunk loader: 32 rows x 8 segs, 8 cp.async/lane ----
    auto load_B = [&](int gg) {
        const uint32_t slot = smB + (uint32_t)(gg % NBUF) * B_CHUNK_B;
        const __nv_bfloat16* bsrc =
            g_Bbf + (size_t)((gg >> 3) * NT + wn * 32) * D_DIM + (gg & 7) * KC;
        #pragma unroll
        for (int it = 0; it < 8; it++) {
            const int i = lane + it * 32;        // 0..255
            const int r = i >> 3, s = i & 7;     // r 0..31
            const int row = wn * 32 + r;
            cp_async16(slot + (uint32_t)(row << 7) +
                           (uint32_t)(((s ^ (row & 7)) & 7) << 4),
                       bsrc + (size_t)r * D_DIM + s * 8);
        }
        cp_commit();
    };

    load_B(0);
    load_B(1);

    const float wp = log1pf(expf(wptr[0]));

    cp_wait<1>();      // A + B0 complete for this thread; B1 may be in flight
    __syncthreads();   // A (cooperative), s_invnx/s_sp visible to all

    float acc[MAXMT][4][4];   // 112 regs
    #pragma unroll
    for (int mt = 0; mt < MAXMT; mt++)
        #pragma unroll
        for (int p = 0; p < 4; p++)
            #pragma unroll
            for (int e = 0; e < 4; e++) acc[mt][p][e] = 0.f;

    float es[MAXMT][2];
    #pragma unroll
    for (int mt = 0; mt < MAXMT; mt++) { es[mt][0] = 0.f; es[mt][1] = 0.f; }

    // ---- MMA over one resident chunk (warp tile nr rows x 32 cols) ----
    auto mma_chunk = [&](int kcA, int slot) {
        const uint32_t Ac = smA + (uint32_t)kcA * A_CH_B;
        const uint32_t Bs = smB + (uint32_t)slot * B_CHUNK_B;
        #pragma unroll
        for (int k16 = 0; k16 < 4; k16++) {
            uint32_t a[MAXMT][4];
            #pragma unroll
            for (int mt = 0; mt < MAXMT; mt++)
                if (mt < nmt)
                    ldsm4(a[mt], sw_addr(Ac, mt * 16 + (lq & 1) * 8 + l7,
                                         k16 * 2 + (lq >> 1)));
            uint32_t b[2][4];
            #pragma unroll
            for (int p2 = 0; p2 < 2; p2++)
                ldsm4(b[p2], sw_addr(Bs, wn * 32 + p2 * 16 + (lq >> 1) * 8 + l7,
                                     k16 * 2 + (lq & 1)));
            #pragma unroll
            for (int p2 = 0; p2 < 2; p2++)
                #pragma unroll
                for (int mt = 0; mt < MAXMT; mt++)
                    if (mt < nmt) {
                        mma16816(acc[mt][p2 * 2],     a[mt], b[p2][0], b[p2][1]);
                        mma16816(acc[mt][p2 * 2 + 1], a[mt], b[p2][2], b[p2][3]);
                    }
        }
    };

    // ---- epilogue of tile t ----
    auto epi_tile = [&](int t) {
        #pragma unroll
        for (int p = 0; p < 4; p++) {
            const int c0  = t * NT + wn * 32 + p * 8 + (lane & 3) * 2;
            const float nm0 = __ldg(&g_invnm[c0]);
            const float nm1 = __ldg(&g_invnm[c0 + 1]);
            #pragma unroll
            for (int mt = 0; mt < MAXMT; mt++) {
                if (mt >= nmt) break;
                const int jr = s16 + mt;   // cluster of this m16 unit
                #pragma unroll
                for (int h = 0; h < 2; h++) {
                    const int rl = mt * 16 + h * 8 + (lane >> 2);
                    const float inx = s_invnx[rl];
                    float s0 = acc[mt][p][h * 2 + 0] * inx * nm0;
                    float s1 = acc[mt][p][h * 2 + 1] * inx * nm1;
                    if (c0     == jr) s0 = s_sp[rl];
                    if (c0 + 1 == jr) s1 = s_sp[rl];
                    es[mt][h] += __expf(wp * s0) + __expf(wp * s1);
                    acc[mt][p][h * 2 + 0] = 0.f;
                    acc[mt][p][h * 2 + 1] = 0.f;
                }
            }
        }
    };

    // ---- main loop: NO cross-warp synchronization ----
    #pragma unroll 1
    for (int t = 0; t < NTILES; t++) {
        #pragma unroll
        for (int kc = 0; kc < 8; kc++) {
            const int g = t * 8 + kc;
            if (g > 0) {
                if (g < NC - 1) cp_wait<1>(); else cp_wait<0>();
                __syncwarp();        // own B chunk g visible warp-wide
            }
            if (g + 2 < NC) load_B(g + 2);
            mma_chunk(kc, g % NBUF);
        }
        epi_tile(t);
    }

    __syncthreads();   // all warps done; safe to alias B ring with s_red

    // ---- reduce exp-sums: 4 lanes per row, then the 8 warp col-slices ----
    #pragma unroll
    for (int mt = 0; mt < MAXMT; mt++) {
        if (mt >= nmt) break;
        #pragma unroll
        for (int h = 0; h < 2; h++) {
            float v = es[mt][h];
            v += __shfl_xor_sync(0xffffffffu, v, 1);
            v += __shfl_xor_sync(0xffffffffu, v, 2);
            if ((lane & 3) == 0)
                s_red[wn * 112 + mt * 16 + h * 8 + (lane >> 2)] = v;
        }
    }
    __syncthreads();
    if (tid < nr) {
        float tot = 0.f;
        #pragma unroll
        for (int w = 0; w < 8; w++) tot += s_red[w * 112 + tid];
        s_rowloss[tid] = logf(tot) - wp * s_sp[tid];
    }
    __syncthreads();
    {
        float v = (tid < nr) ? s_rowloss[tid] : 0.f;
        #pragma unroll
        for (int off = 16; off; off >>= 1) v += __shfl_down_sync(0xffffffffu, v, off);
        if (lane == 0) s_part[wn] = v;
    }
    __syncthreads();
    if (tid == 0) {
        float t = 0.f;
        #pragma unroll
        for (int i = 0; i < 8; i++) t += s_part[i];
        atomicAdd(out, t * (1.f / (float)NROWS));
    }
}

extern "C" void kernel_launch(void* const* d_in, const int* in_sizes, int n_in,
                              void* d_out, int out_size)
{
    const float* x = (const float*)d_in[0];
    const float* w = (const float*)d_in[1];
    // b cancels: lse(wp*sim + b) - (wp*sim_pos + b) is b-independent.
    float* out = (float*)d_out;

    cudaFuncSetAttribute(k2_gemm_lse, cudaFuncAttributeMaxDynamicSharedMemorySize, DYN_SMEM);

    k1_stats<<<C_CLUST, 256>>>(x, out);
    k2_gemm_lse<<<NCTA, NTHREADS, DYN_SMEM>>>(w, out);
}